// round 4
// baseline (speedup 1.0000x reference)
#include <cuda_runtime.h>
#include <stdint.h>

#define NUM_GRAPHS 4096
#define EMB_DIM 128
#define THREADS 128

__global__ __launch_bounds__(THREADS)
void att_pool_kernel(const float* __restrict__ x,
                     const void* __restrict__ batch_raw,
                     const float* __restrict__ w,
                     float* __restrict__ out,
                     int n_nodes, int out_size)
{
    const int g = blockIdx.x;
    const int t = threadIdx.x;
    const int warp = t >> 5;
    const int lane = t & 31;

    __shared__ float accs[4][EMB_DIM];
    __shared__ float ls[4];
    __shared__ int s_start, s_end;

    // Binary search contiguous [start, end) for graph g (batch is sorted).
    // dtype probe: as int32, index n-1 holds the last (largest) graph id != 0;
    // as int64 (values < 2^31, little-endian), that word is an upper half == 0.
    if (t == 0) {
        const int* b32 = (const int*)batch_raw;
        const long long* b64 = (const long long*)batch_raw;
        const bool is64 = (b32[n_nodes - 1] == 0);

        long long gv = (long long)g;
        int lo = 0, hi = n_nodes;
        while (lo < hi) {
            int mid = (lo + hi) >> 1;
            long long v = is64 ? b64[mid] : (long long)b32[mid];
            if (v < gv) lo = mid + 1; else hi = mid;
        }
        s_start = lo;
        hi = n_nodes;
        const long long gv1 = gv + 1;
        while (lo < hi) {
            int mid = (lo + hi) >> 1;
            long long v = is64 ? b64[mid] : (long long)b32[mid];
            if (v < gv1) lo = mid + 1; else hi = mid;
        }
        s_end = lo;
    }

    // weight float4 for this lane (same for all warps; L1/L2 resident)
    const float4 wv = ((const float4*)w)[lane];

    __syncthreads();
    const int start = s_start;
    const int end   = s_end;
    const int cnt   = end - start;

    // One warp per node row, 4 rows in flight (MLP=4 per warp).
    // x is read exactly once; softmax without max-subtraction (shift-invariant,
    // |score| small enough for fp32 exp).
    float4 acc = make_float4(0.f, 0.f, 0.f, 0.f);
    float  l   = 0.f;

    int j = start + warp;
    for (; j + 12 < end; j += 16) {
        // group the 4 independent loads first (MLP)
        const float4 xv0 = ((const float4*)(x + (size_t)(j     ) * EMB_DIM))[lane];
        const float4 xv1 = ((const float4*)(x + (size_t)(j +  4) * EMB_DIM))[lane];
        const float4 xv2 = ((const float4*)(x + (size_t)(j +  8) * EMB_DIM))[lane];
        const float4 xv3 = ((const float4*)(x + (size_t)(j + 12) * EMB_DIM))[lane];

        float p0 = xv0.x * wv.x + xv0.y * wv.y + xv0.z * wv.z + xv0.w * wv.w;
        float p1 = xv1.x * wv.x + xv1.y * wv.y + xv1.z * wv.z + xv1.w * wv.w;
        float p2 = xv2.x * wv.x + xv2.y * wv.y + xv2.z * wv.z + xv2.w * wv.w;
        float p3 = xv3.x * wv.x + xv3.y * wv.y + xv3.z * wv.z + xv3.w * wv.w;
        #pragma unroll
        for (int o = 16; o; o >>= 1) {
            p0 += __shfl_xor_sync(0xffffffffu, p0, o);
            p1 += __shfl_xor_sync(0xffffffffu, p1, o);
            p2 += __shfl_xor_sync(0xffffffffu, p2, o);
            p3 += __shfl_xor_sync(0xffffffffu, p3, o);
        }
        const float e0 = __expf(p0);
        const float e1 = __expf(p1);
        const float e2 = __expf(p2);
        const float e3 = __expf(p3);
        acc.x += e0 * xv0.x; acc.y += e0 * xv0.y; acc.z += e0 * xv0.z; acc.w += e0 * xv0.w;
        acc.x += e1 * xv1.x; acc.y += e1 * xv1.y; acc.z += e1 * xv1.z; acc.w += e1 * xv1.w;
        acc.x += e2 * xv2.x; acc.y += e2 * xv2.y; acc.z += e2 * xv2.z; acc.w += e2 * xv2.w;
        acc.x += e3 * xv3.x; acc.y += e3 * xv3.y; acc.z += e3 * xv3.z; acc.w += e3 * xv3.w;
        l += (e0 + e1) + (e2 + e3);
    }
    for (; j < end; j += 4) {
        const float4 xv = ((const float4*)(x + (size_t)j * EMB_DIM))[lane];
        float p = xv.x * wv.x + xv.y * wv.y + xv.z * wv.z + xv.w * wv.w;
        #pragma unroll
        for (int o = 16; o; o >>= 1) p += __shfl_xor_sync(0xffffffffu, p, o);
        const float e = __expf(p);
        acc.x += e * xv.x; acc.y += e * xv.y;
        acc.z += e * xv.z; acc.w += e * xv.w;
        l += e;
    }

    // combine the 4 warps
    ((float4*)accs[warp])[lane] = acc;
    if (lane == 0) ls[warp] = l;
    __syncthreads();

    const float a = accs[0][t] + accs[1][t] + accs[2][t] + accs[3][t];
    const float L = ls[0] + ls[1] + ls[2] + ls[3];

    const float denom = fmaxf(L, 1e-30f) * fmaxf((float)cnt, 1.0f);
    out[(size_t)g * EMB_DIM + t] = a / denom;

    // second tuple element: att_weight passthrough
    if (g == 0 && out_size >= NUM_GRAPHS * EMB_DIM + EMB_DIM) {
        out[NUM_GRAPHS * EMB_DIM + t] = w[t];
    }
}

extern "C" void kernel_launch(void* const* d_in, const int* in_sizes, int n_in,
                              void* d_out, int out_size)
{
    const float* x     = (const float*)d_in[0];
    const void*  batch = d_in[1];
    const float* w     = (const float*)d_in[2];
    float*       out   = (float*)d_out;
    const int n_nodes = in_sizes[1];

    att_pool_kernel<<<NUM_GRAPHS, THREADS>>>(x, batch, w, out, n_nodes, out_size);
}